// round 1
// baseline (speedup 1.0000x reference)
#include <cuda_runtime.h>
#include <math.h>

// ---------------- problem constants ----------------
#define NT   16384      // B*S tokens
#define H    2048
#define E    256
#define THID 512
#define T    128
#define NREG 64         // NUM_REGISTERED_TOOLS
#define TB   8          // tokens per selector CTA

// ---------------- scratch (device globals: no allocs allowed) ----------------
__device__ float g_hid[(long)NT * THID];      // 32 MB, reused for sel-h1 / pg-h1 / ri-h1
__device__ float g_toolres[(long)NT * H];     // 128 MB
__device__ int   g_active[NT];
__device__ int   g_tool[NT];
__device__ int   g_count[1];

// ---------------- tiny kernels ----------------
__global__ void init_kernel() { g_count[0] = 0; }

__global__ void copy_kernel(const float* __restrict__ src, float* __restrict__ dst) {
    long i = ((long)blockIdx.x * 256 + threadIdx.x) * 4;
    float4 v = *(const float4*)(src + i);
    *(float4*)(dst + i) = v;
}

// ---------------- warp helpers (16-lane segments) ----------------
__device__ __forceinline__ void argmax16(float& v, int& i) {
#pragma unroll
    for (int off = 8; off >= 1; off >>= 1) {
        float ov = __shfl_xor_sync(0xffffffffu, v, off, 16);
        int   oi = __shfl_xor_sync(0xffffffffu, i, off, 16);
        if (ov > v || (ov == v && oi < i)) { v = ov; i = oi; }
    }
}
__device__ __forceinline__ float sum16(float v) {
#pragma unroll
    for (int off = 8; off >= 1; off >>= 1)
        v += __shfl_xor_sync(0xffffffffu, v, off, 16);
    return v;
}

// ---------------- fused selector: logits, softmax, top-3, gate, compaction ----------------
__global__ __launch_bounds__(128) void selector_kernel(
    const float* __restrict__ sel_w2,   // [512,128]
    const float* __restrict__ sel_b2,   // [128]
    const float* __restrict__ hidden,   // [NT,2048]
    const float* __restrict__ gate_w,   // [2048]
    const float* __restrict__ gate_b,   // [1]
    float* __restrict__ out_probs,      // [NT,128] (may be null)
    float* __restrict__ out_should)     // [NT]     (may be null)
{
    int tid = threadIdx.x;
    int t0  = blockIdx.x * TB;
    int q   = tid >> 4;      // token within CTA (0..7)
    int tx  = tid & 15;      // 16 lanes per token
    int t   = t0 + q;

    __shared__ float sh1[TB][THID];
    for (int i = tid; i < TB * THID; i += 128)
        sh1[i >> 9][i & 511] = g_hid[(long)t0 * THID + i];
    __syncthreads();

    // logits for cols tx*8 .. tx*8+7 of token q (exact fp32 — protects top-k)
    float lg[8];
    const float* b2 = sel_b2 + tx * 8;
#pragma unroll
    for (int j = 0; j < 8; j++) lg[j] = b2[j];
    const float* w2 = sel_w2 + tx * 8;
    for (int k = 0; k < THID; k++) {
        float a = sh1[q][k];
        float4 w0 = *(const float4*)(w2 + (long)k * T);
        float4 w1 = *(const float4*)(w2 + (long)k * T + 4);
        lg[0] = fmaf(a, w0.x, lg[0]); lg[1] = fmaf(a, w0.y, lg[1]);
        lg[2] = fmaf(a, w0.z, lg[2]); lg[3] = fmaf(a, w0.w, lg[3]);
        lg[4] = fmaf(a, w1.x, lg[4]); lg[5] = fmaf(a, w1.y, lg[5]);
        lg[6] = fmaf(a, w1.z, lg[6]); lg[7] = fmaf(a, w1.w, lg[7]);
    }

    // gate: sigmoid(x)>0.5 <=> x>0 (fp32 to protect the sign)
    float gp = 0.f;
    const float* hrow = hidden + (long)t * H;
    for (int k = tx; k < H; k += 16) gp = fmaf(hrow[k], gate_w[k], gp);
    gp = sum16(gp);
    bool should = (gp + gate_b[0]) > 0.f;

    // top-3, jax tie-break: higher value, tie -> lower index
    int topi[3];
    unsigned selmask = 0;
    float mx = 0.f;
#pragma unroll
    for (int r = 0; r < 3; r++) {
        float v = -3.4e38f; int bi = 1 << 30;
#pragma unroll
        for (int j = 0; j < 8; j++) {
            if (!((selmask >> j) & 1)) {
                int c = tx * 8 + j;
                if (lg[j] > v || (lg[j] == v && c < bi)) { v = lg[j]; bi = c; }
            }
        }
        argmax16(v, bi);
        if (r == 0) mx = v;
        topi[r] = bi;
        if ((bi >> 3) == tx) selmask |= 1u << (bi & 7);
    }

    // softmax
    float e[8], s = 0.f;
#pragma unroll
    for (int j = 0; j < 8; j++) { e[j] = expf(lg[j] - mx); s += e[j]; }
    s = sum16(s);
    if (out_probs) {
        float4 p0 = make_float4(e[0]/s, e[1]/s, e[2]/s, e[3]/s);
        float4 p1 = make_float4(e[4]/s, e[5]/s, e[6]/s, e[7]/s);
        *(float4*)(out_probs + (long)t * T + tx * 8)     = p0;
        *(float4*)(out_probs + (long)t * T + tx * 8 + 4) = p1;
    }

    if (tx == 0) {
        if (out_should) out_should[t] = should ? 1.0f : 0.0f;
        int last = -1, tool = 0;
#pragma unroll
        for (int k = 0; k < 3; k++)
            if (should && topi[k] < NREG) { last = k; tool = topi[k]; }
        if (last >= 0) {
            int pos = atomicAdd(g_count, 1);
            g_active[pos] = t;
            g_tool[pos]   = tool;
        }
    }
}

// ---------------- generic SGEMM with gather/concat/scatter ----------------
// mode: 0 direct rows, 1 gather token + concat emb, 2 gather token + concat toolres
// asel: 0 A=Aext, 1 A=g_hid       dsel: 0 C=g_hid, 1 C=g_toolres, 2 C=Cext
__global__ __launch_bounds__(256, 2) void gemm_kernel(
    int mode, int asel, int dsel, int do_relu, int do_scatter, int use_count,
    const float* __restrict__ Aext, int lda,
    const float* __restrict__ Bext,          // emb table (mode 1)
    int splitK,
    const float* __restrict__ W, int ldw,    // [K, N] row-major
    const float* __restrict__ bias,
    float* __restrict__ Cext, int ldc,
    int K, int Mfixed)
{
    __shared__ float As[16][132];
    __shared__ float Ws[16][128];

    int Meff = use_count ? g_count[0] : Mfixed;
    int m0 = blockIdx.y * 128;
    if (m0 >= Meff) return;
    int n0 = blockIdx.x * 128;
    int tid = threadIdx.x;

    const float* A0 = asel ? g_hid : Aext;

    // A-loader: two rows per thread (ra, ra+64), 4 k's each
    int ra = tid >> 2;
    int kq = (tid & 3) * 4;
    const float* baseP[2];
    const float* baseS[2];
#pragma unroll
    for (int i = 0; i < 2; i++) {
        int r = m0 + ra + i * 64;
        if (mode == 0) {
            baseP[i] = A0 + (long)r * lda;
            baseS[i] = baseP[i];
        } else {
            int rr = (r < Meff) ? r : (Meff - 1);   // clamp padded rows: deterministic+finite
            int tok = g_active[rr];
            baseP[i] = Aext + (long)tok * lda;
            baseS[i] = (mode == 1) ? (Bext + (long)g_tool[rr] * E)
                                   : (g_toolres + (long)rr * H);
        }
    }

    int wk = tid >> 5;           // 0..7
    int wn = (tid & 31) * 4;

    float acc[8][8];
#pragma unroll
    for (int i = 0; i < 8; i++)
#pragma unroll
        for (int j = 0; j < 8; j++) acc[i][j] = 0.f;

    int tx = tid & 15, ty = tid >> 4;

    for (int k0 = 0; k0 < K; k0 += 16) {
#pragma unroll
        for (int i = 0; i < 2; i++) {
            const float* src = (k0 < splitK) ? (baseP[i] + k0 + kq)
                                             : (baseS[i] + (k0 - splitK) + kq);
            float4 v = *(const float4*)src;
            int m = ra + i * 64;
            As[kq + 0][m] = v.x; As[kq + 1][m] = v.y;
            As[kq + 2][m] = v.z; As[kq + 3][m] = v.w;
        }
#pragma unroll
        for (int i = 0; i < 2; i++) {
            int k = wk + i * 8;
            float4 v = *(const float4*)(W + (long)(k0 + k) * ldw + n0 + wn);
            *(float4*)&Ws[k][wn] = v;
        }
        __syncthreads();
#pragma unroll
        for (int kk = 0; kk < 16; kk++) {
            float a[8], b[8];
            *(float4*)(a)     = *(const float4*)&As[kk][ty * 8];
            *(float4*)(a + 4) = *(const float4*)&As[kk][ty * 8 + 4];
            *(float4*)(b)     = *(const float4*)&Ws[kk][tx * 8];
            *(float4*)(b + 4) = *(const float4*)&Ws[kk][tx * 8 + 4];
#pragma unroll
            for (int i = 0; i < 8; i++)
#pragma unroll
                for (int j = 0; j < 8; j++)
                    acc[i][j] = fmaf(a[i], b[j], acc[i][j]);
        }
        __syncthreads();
    }

    float* Cbase = (dsel == 0) ? g_hid : ((dsel == 1) ? g_toolres : Cext);
#pragma unroll
    for (int i = 0; i < 8; i++) {
        int r = m0 + ty * 8 + i;
        if (do_scatter && r >= Meff) continue;   // never scatter padded rows
        long row = do_scatter ? (long)g_active[r] : (long)r;
        float* cp = Cbase + row * ldc + n0 + tx * 8;
#pragma unroll
        for (int jj = 0; jj < 8; jj += 4) {
            float4 v;
            v.x = acc[i][jj + 0] + bias[n0 + tx * 8 + jj + 0];
            v.y = acc[i][jj + 1] + bias[n0 + tx * 8 + jj + 1];
            v.z = acc[i][jj + 2] + bias[n0 + tx * 8 + jj + 2];
            v.w = acc[i][jj + 3] + bias[n0 + tx * 8 + jj + 3];
            if (do_relu) {
                v.x = fmaxf(v.x, 0.f); v.y = fmaxf(v.y, 0.f);
                v.z = fmaxf(v.z, 0.f); v.w = fmaxf(v.w, 0.f);
            }
            *(float4*)(cp + jj) = v;
        }
    }
}

// ---------------- launch ----------------
extern "C" void kernel_launch(void* const* d_in, const int* in_sizes, int n_in,
                              void* d_out, int out_size)
{
    const float* hidden = (const float*)d_in[0];
    const float* emb    = (const float*)d_in[1];
    const float* gate_w = (const float*)d_in[2];
    const float* gate_b = (const float*)d_in[3];
    const float* sel_w1 = (const float*)d_in[4];
    const float* sel_b1 = (const float*)d_in[5];
    const float* sel_w2 = (const float*)d_in[6];
    const float* sel_b2 = (const float*)d_in[7];
    const float* pg_w1  = (const float*)d_in[8];
    const float* pg_b1  = (const float*)d_in[9];
    const float* pg_w2  = (const float*)d_in[10];
    const float* pg_b2  = (const float*)d_in[11];
    const float* ri_w1  = (const float*)d_in[12];
    const float* ri_b1  = (const float*)d_in[13];
    const float* ri_w2  = (const float*)d_in[14];
    const float* ri_b2  = (const float*)d_in[15];

    float* out       = (float*)d_out;
    float* out_enh   = out;
    float* out_probs  = ((long)out_size >= (long)NT * (H + T))     ? out + (long)NT * H       : nullptr;
    float* out_should = ((long)out_size >= (long)NT * (H + T + 1)) ? out + (long)NT * (H + T) : nullptr;

    // 0) reset compaction counter
    init_kernel<<<1, 1>>>();

    // 1) default: enhanced = hidden_states (active rows overwritten at the end)
    copy_kernel<<<((long)NT * H) / 4 / 256, 256>>>(hidden, out_enh);

    // 2) selector layer 1: h1 = relu(hidden @ sel_w1 + b1)   [NT,512]
    gemm_kernel<<<dim3(THID / 128, NT / 128), 256>>>(
        0, 0, 0, /*relu*/1, /*scatter*/0, /*count*/0,
        hidden, H, nullptr, /*splitK*/H,
        sel_w1, THID, sel_b1, nullptr, THID, H, NT);

    // 3) logits + softmax + top-3 + gate + compaction
    selector_kernel<<<NT / TB, 128>>>(sel_w2, sel_b2, hidden, gate_w, gate_b,
                                      out_probs, out_should);

    // 4) pg layer 1 (active rows): relu(concat(h, emb[tool]) @ pg_w1 + b1) -> g_hid
    gemm_kernel<<<dim3(THID / 128, NT / 128), 256>>>(
        1, 0, 0, 1, 0, 1,
        hidden, H, emb, /*splitK*/H,
        pg_w1, THID, pg_b1, nullptr, THID, H + E, NT);

    // 5) pg layer 2: tool_result = g_hid @ pg_w2 + b2 -> g_toolres
    gemm_kernel<<<dim3(H / 128, NT / 128), 256>>>(
        0, 1, 1, 0, 0, 1,
        nullptr, THID, nullptr, /*splitK*/THID,
        pg_w2, H, pg_b2, nullptr, H, THID, NT);

    // 6) ri layer 1: relu(concat(h, tool_result) @ ri_w1 + b1) -> g_hid
    gemm_kernel<<<dim3(THID / 128, NT / 128), 256>>>(
        2, 0, 0, 1, 0, 1,
        hidden, H, nullptr, /*splitK*/H,
        ri_w1, THID, ri_b1, nullptr, THID, 2 * H, NT);

    // 7) ri layer 2: integrated = g_hid @ ri_w2 + b2, scatter into enhanced
    gemm_kernel<<<dim3(H / 128, NT / 128), 256>>>(
        0, 1, 2, 0, 1, 1,
        nullptr, THID, nullptr, /*splitK*/THID,
        ri_w2, H, ri_b2, out_enh, H, THID, NT);
}

// round 3
// speedup vs baseline: 1.5686x; 1.5686x over previous
#include <cuda_runtime.h>
#include <cuda_bf16.h>
#include <math.h>
#include <stdint.h>

// ---------------- problem constants ----------------
#define NT   16384      // B*S tokens
#define H    2048
#define E    256
#define THID 512
#define T    128
#define NREG 64         // NUM_REGISTERED_TOOLS

// ---------------- scratch (device globals: no allocs allowed) ----------------
__device__ float g_hid[(long)NT * THID];      // 32 MB: sel-h1, then pg-h1 / ri-h1 (compact)
__device__ float g_toolres[(long)NT * H];     // 128 MB
__device__ float g_logits[(long)NT * T];      // 8 MB
__device__ float g_gate[NT];
__device__ int   g_active[NT];
__device__ int   g_tool[NT];
__device__ int   g_count[1];

// ---------------- tiny kernels ----------------
__global__ void init_kernel() { g_count[0] = 0; }

// copy hidden -> out AND compute gate dot product (single pass over hidden)
__global__ __launch_bounds__(256) void copy_gate_kernel(
    const float* __restrict__ src, const float* __restrict__ gw,
    float* __restrict__ dst)
{
    __shared__ float red[8];
    int t = blockIdx.x, tid = threadIdx.x;
    long base = (long)t * H + tid * 8;
    float4 a = *(const float4*)(src + base);
    float4 b = *(const float4*)(src + base + 4);
    *(float4*)(dst + base)     = a;
    *(float4*)(dst + base + 4) = b;
    float4 w0 = *(const float4*)(gw + tid * 8);
    float4 w1 = *(const float4*)(gw + tid * 8 + 4);
    float acc = a.x*w0.x + a.y*w0.y + a.z*w0.z + a.w*w0.w
              + b.x*w1.x + b.y*w1.y + b.z*w1.z + b.w*w1.w;
#pragma unroll
    for (int off = 16; off >= 1; off >>= 1)
        acc += __shfl_xor_sync(0xffffffffu, acc, off);
    if ((tid & 31) == 0) red[tid >> 5] = acc;
    __syncthreads();
    if (tid == 0) {
        float s = 0.f;
#pragma unroll
        for (int i = 0; i < 8; i++) s += red[i];
        g_gate[t] = s;
    }
}

// top-k/softmax/gate/compaction: one warp per token, reads g_logits
__global__ __launch_bounds__(256) void topk_kernel(
    const float* __restrict__ gate_b,
    float* __restrict__ out_probs, float* __restrict__ out_should)
{
    int t = blockIdx.x * 8 + (threadIdx.x >> 5);
    int l = threadIdx.x & 31;
    float4 v = *(const float4*)(g_logits + (long)t * T + l * 4);
    float lg[4] = {v.x, v.y, v.z, v.w};
    int topi[3];
    unsigned mask = 0;
    float mx = 0.f;
#pragma unroll
    for (int r = 0; r < 3; r++) {
        float bv = -3.4e38f; int bi = 1 << 30;
#pragma unroll
        for (int j = 0; j < 4; j++) {
            if (!((mask >> j) & 1)) {
                int c = l * 4 + j;
                if (lg[j] > bv || (lg[j] == bv && c < bi)) { bv = lg[j]; bi = c; }
            }
        }
#pragma unroll
        for (int off = 16; off >= 1; off >>= 1) {
            float ov = __shfl_xor_sync(0xffffffffu, bv, off);
            int   oi = __shfl_xor_sync(0xffffffffu, bi, off);
            if (ov > bv || (ov == bv && oi < bi)) { bv = ov; bi = oi; }
        }
        if (r == 0) mx = bv;
        topi[r] = bi;
        if ((bi >> 2) == l) mask |= 1u << (bi & 3);
    }
    float e[4], s = 0.f;
#pragma unroll
    for (int j = 0; j < 4; j++) { e[j] = expf(lg[j] - mx); s += e[j]; }
#pragma unroll
    for (int off = 16; off >= 1; off >>= 1)
        s += __shfl_xor_sync(0xffffffffu, s, off);
    if (out_probs)
        *(float4*)(out_probs + (long)t * T + l * 4) = make_float4(e[0]/s, e[1]/s, e[2]/s, e[3]/s);
    if (l == 0) {
        bool should = (g_gate[t] + gate_b[0]) > 0.f;
        if (out_should) out_should[t] = should ? 1.0f : 0.0f;
        int last = -1, tool = 0;
#pragma unroll
        for (int k = 0; k < 3; k++)
            if (should && topi[k] < NREG) { last = k; tool = topi[k]; }
        if (last >= 0) {
            int pos = atomicAdd(g_count, 1);
            g_active[pos] = t;
            g_tool[pos]   = tool;
        }
    }
}

// ---------------- fp32 FFMA GEMM (selector path: exactness protects top-k) ----------------
// asel: 0 A=Aext, 1 A=g_hid.   dsel: 0 g_hid, 3 g_logits
__global__ __launch_bounds__(256, 2) void gemm_kernel(
    int asel, int dsel, int do_relu,
    const float* __restrict__ Aext, int lda,
    const float* __restrict__ W, int ldw,    // [K, N] row-major
    const float* __restrict__ bias,
    int ldc, int K)
{
    __shared__ float As[16][132];
    __shared__ float Ws[16][128];

    int m0 = blockIdx.y * 128;
    int n0 = blockIdx.x * 128;
    int tid = threadIdx.x;
    const float* A0 = asel ? g_hid : Aext;

    int ra = tid >> 2;
    int kq = (tid & 3) * 4;
    const float* baseP[2];
#pragma unroll
    for (int i = 0; i < 2; i++)
        baseP[i] = A0 + (long)(m0 + ra + i * 64) * lda;

    int wk = tid >> 5;
    int wn = (tid & 31) * 4;

    float acc[8][8];
#pragma unroll
    for (int i = 0; i < 8; i++)
#pragma unroll
        for (int j = 0; j < 8; j++) acc[i][j] = 0.f;

    int tx = tid & 15, ty = tid >> 4;

    for (int k0 = 0; k0 < K; k0 += 16) {
#pragma unroll
        for (int i = 0; i < 2; i++) {
            float4 v = *(const float4*)(baseP[i] + k0 + kq);
            int m = ra + i * 64;
            As[kq + 0][m] = v.x; As[kq + 1][m] = v.y;
            As[kq + 2][m] = v.z; As[kq + 3][m] = v.w;
        }
#pragma unroll
        for (int i = 0; i < 2; i++) {
            int k = wk + i * 8;
            float4 v = *(const float4*)(W + (long)(k0 + k) * ldw + n0 + wn);
            *(float4*)&Ws[k][wn] = v;
        }
        __syncthreads();
#pragma unroll
        for (int kk = 0; kk < 16; kk++) {
            float a[8], b[8];
            *(float4*)(a)     = *(const float4*)&As[kk][ty * 8];
            *(float4*)(a + 4) = *(const float4*)&As[kk][ty * 8 + 4];
            *(float4*)(b)     = *(const float4*)&Ws[kk][tx * 8];
            *(float4*)(b + 4) = *(const float4*)&Ws[kk][tx * 8 + 4];
#pragma unroll
            for (int i = 0; i < 8; i++)
#pragma unroll
                for (int j = 0; j < 8; j++)
                    acc[i][j] = fmaf(a[i], b[j], acc[i][j]);
        }
        __syncthreads();
    }

    float* Cbase = (dsel == 0) ? g_hid : g_logits;
#pragma unroll
    for (int i = 0; i < 8; i++) {
        long row = m0 + ty * 8 + i;
        float* cp = Cbase + row * ldc + n0 + tx * 8;
#pragma unroll
        for (int jj = 0; jj < 8; jj += 4) {
            float4 v;
            v.x = acc[i][jj + 0] + bias[n0 + tx * 8 + jj + 0];
            v.y = acc[i][jj + 1] + bias[n0 + tx * 8 + jj + 1];
            v.z = acc[i][jj + 2] + bias[n0 + tx * 8 + jj + 2];
            v.w = acc[i][jj + 3] + bias[n0 + tx * 8 + jj + 3];
            if (do_relu) {
                v.x = fmaxf(v.x, 0.f); v.y = fmaxf(v.y, 0.f);
                v.z = fmaxf(v.z, 0.f); v.w = fmaxf(v.w, 0.f);
            }
            *(float4*)(cp + jj) = v;
        }
    }
}

// ---------------- mma.sync bf16 3-pass GEMM (pg/ri path, value-only precision) ----------------
// CTA tile M=64, N=128, Kstage=32, double-buffered smem.
// Split: x = hi + lo (bf16); D += Ahi*Whi + Alo*Whi + Ahi*Wlo  (error ~2^-18).
// mode: 0 direct rows, 1 gather token + concat emb, 2 gather token + concat toolres
// asel: 0 A=Aext, 1 A=g_hid.   dsel: 0 g_hid, 1 g_toolres, 2 Cext(+scatter)

#define A_STRIDE 72                     // bytes per A smem row (32 bf16 + pad)
#define W_STRIDE 68                     // bytes per W smem row (32 bf16 + pad)
#define OFF_A_HI 0
#define OFF_A_LO (64 * A_STRIDE)                    // 4608
#define OFF_W_HI (2 * 64 * A_STRIDE)                // 9216
#define OFF_W_LO (OFF_W_HI + 128 * W_STRIDE)        // 17920
#define BUF_SZ   (OFF_W_LO + 128 * W_STRIDE)        // 26624
#define MMA_SMEM (2 * BUF_SZ)                       // 53248

// W smem bank swizzle: kp (= k>>1) XORed with bits 5..6 of n (store-conflict-free)
__device__ __forceinline__ int w_off(int n, int kp) {
    return n * W_STRIDE + 4 * (kp ^ ((n >> 5) & 3));
}

__device__ __forceinline__ void mma16816(float* c, const uint32_t* a, const uint32_t* b) {
    asm volatile(
        "mma.sync.aligned.m16n8k16.row.col.f32.bf16.bf16.f32 "
        "{%0,%1,%2,%3}, {%4,%5,%6,%7}, {%8,%9}, {%0,%1,%2,%3};\n"
        : "+f"(c[0]), "+f"(c[1]), "+f"(c[2]), "+f"(c[3])
        : "r"(a[0]), "r"(a[1]), "r"(a[2]), "r"(a[3]), "r"(b[0]), "r"(b[1]));
}

__device__ __forceinline__ uint32_t pack_hi2(float x, float y) {
    __nv_bfloat16 hx = __float2bfloat16(x), hy = __float2bfloat16(y);
    return (uint32_t)__bfloat16_as_ushort(hx) | ((uint32_t)__bfloat16_as_ushort(hy) << 16);
}
__device__ __forceinline__ uint32_t pack_lo2(float x, float y) {
    __nv_bfloat16 hx = __float2bfloat16(x), hy = __float2bfloat16(y);
    __nv_bfloat16 lx = __float2bfloat16(x - __bfloat162float(hx));
    __nv_bfloat16 ly = __float2bfloat16(y - __bfloat162float(hy));
    return (uint32_t)__bfloat16_as_ushort(lx) | ((uint32_t)__bfloat16_as_ushort(ly) << 16);
}

__global__ __launch_bounds__(256) void mma_gemm_kernel(
    int mode, int asel, int dsel, int do_relu, int do_scatter,
    const float* __restrict__ Aext, int lda,
    const float* __restrict__ Bsec, int splitK,
    const float* __restrict__ W, int ldw,
    const float* __restrict__ bias,
    float* __restrict__ Cext, int ldc, int K)
{
    extern __shared__ __align__(16) char smem[];
    int Meff = g_count[0];
    int m0 = blockIdx.y * 64;
    if (m0 >= Meff) return;
    int n0 = blockIdx.x * 128;
    int tid = threadIdx.x;
    int wid = tid >> 5;
    int lane = tid & 31;
    int wm = wid & 1;       // m half (32 rows)
    int wn = wid >> 1;      // n quarter (32 cols)

    // ---- A loader mapping: 4 threads per row, 8 k's each ----
    int arow = tid >> 2;
    int ak   = (tid & 3) * 8;
    const float* A0 = asel ? g_hid : Aext;
    const float* prim;
    const float* sec;
    {
        int rg = m0 + arow;
        if (mode == 0) {
            prim = A0 + (long)rg * lda;
            sec  = prim;
        } else {
            int rr  = (rg < Meff) ? rg : (Meff - 1);
            int tok = g_active[rr];
            prim = Aext + (long)tok * lda;
            sec  = (mode == 1) ? (Bsec + (long)g_tool[rr] * E)
                               : (g_toolres + (long)rr * H);
        }
    }
    // ---- W loader mapping: 32 threads across n (coalesced), 8 k rows base ----
    int wn4 = (tid & 31) * 4;
    int wkb = tid >> 5;

    float4 aq0, aq1;
    float4 wq[4];
    int S = K / 32;

    float acc[2][4][4];
#pragma unroll
    for (int i = 0; i < 2; i++)
#pragma unroll
        for (int j = 0; j < 4; j++)
#pragma unroll
            for (int q = 0; q < 4; q++) acc[i][j][q] = 0.f;

    // ---- prologue: load + store stage 0 ----
    {
        int k0 = ak;
        const float* src = (k0 < splitK) ? (prim + k0) : (sec + (k0 - splitK));
        aq0 = *(const float4*)(src);
        aq1 = *(const float4*)(src + 4);
#pragma unroll
        for (int i = 0; i < 4; i++)
            wq[i] = *(const float4*)(W + (long)(wkb + 8 * i) * ldw + n0 + wn4);
    }
    {
        char* bp = smem;
        int ab = arow * A_STRIDE + 2 * ak;
        *(uint32_t*)(bp + OFF_A_HI + ab)      = pack_hi2(aq0.x, aq0.y);
        *(uint32_t*)(bp + OFF_A_HI + ab + 4)  = pack_hi2(aq0.z, aq0.w);
        *(uint32_t*)(bp + OFF_A_HI + ab + 8)  = pack_hi2(aq1.x, aq1.y);
        *(uint32_t*)(bp + OFF_A_HI + ab + 12) = pack_hi2(aq1.z, aq1.w);
        *(uint32_t*)(bp + OFF_A_LO + ab)      = pack_lo2(aq0.x, aq0.y);
        *(uint32_t*)(bp + OFF_A_LO + ab + 4)  = pack_lo2(aq0.z, aq0.w);
        *(uint32_t*)(bp + OFF_A_LO + ab + 8)  = pack_lo2(aq1.x, aq1.y);
        *(uint32_t*)(bp + OFF_A_LO + ab + 12) = pack_lo2(aq1.z, aq1.w);
        const float* wv = (const float*)wq;
#pragma unroll
        for (int i = 0; i < 4; i++) {
            int k = wkb + 8 * i;
#pragma unroll
            for (int j = 0; j < 4; j++) {
                float x = wv[i * 4 + j];
                int n = wn4 + j;
                int off = w_off(n, k >> 1) + (k & 1) * 2;
                __nv_bfloat16 hx = __float2bfloat16(x);
                __nv_bfloat16 lx = __float2bfloat16(x - __bfloat162float(hx));
                *(uint16_t*)(bp + OFF_W_HI + off) = __bfloat16_as_ushort(hx);
                *(uint16_t*)(bp + OFF_W_LO + off) = __bfloat16_as_ushort(lx);
            }
        }
    }
    __syncthreads();

    int g  = lane >> 2;
    int j2 = lane & 3;

    for (int s = 0; s < S; s++) {
        // prefetch next stage into registers
        if (s + 1 < S) {
            int k0 = (s + 1) * 32 + ak;
            const float* src = (k0 < splitK) ? (prim + k0) : (sec + (k0 - splitK));
            aq0 = *(const float4*)(src);
            aq1 = *(const float4*)(src + 4);
#pragma unroll
            for (int i = 0; i < 4; i++)
                wq[i] = *(const float4*)(W + (long)((s + 1) * 32 + wkb + 8 * i) * ldw + n0 + wn4);
        }
        // compute current stage
        {
            char* bp = smem + (s & 1) * BUF_SZ;
            const char* Ah = bp + OFF_A_HI;
            const char* Al = bp + OFF_A_LO;
            const char* Wh = bp + OFF_W_HI;
            const char* Wl = bp + OFF_W_LO;
#pragma unroll
            for (int ks = 0; ks < 2; ks++) {
                int kk = ks * 16 + j2 * 2;
                uint32_t ahi[2][4], alo[2][4];
#pragma unroll
                for (int mi = 0; mi < 2; mi++) {
                    int row = wm * 32 + mi * 16 + g;
                    int b0 = row * A_STRIDE + 2 * kk;
                    ahi[mi][0] = *(const uint32_t*)(Ah + b0);
                    ahi[mi][1] = *(const uint32_t*)(Ah + b0 + 8 * A_STRIDE);
                    ahi[mi][2] = *(const uint32_t*)(Ah + b0 + 16);
                    ahi[mi][3] = *(const uint32_t*)(Ah + b0 + 8 * A_STRIDE + 16);
                    alo[mi][0] = *(const uint32_t*)(Al + b0);
                    alo[mi][1] = *(const uint32_t*)(Al + b0 + 8 * A_STRIDE);
                    alo[mi][2] = *(const uint32_t*)(Al + b0 + 16);
                    alo[mi][3] = *(const uint32_t*)(Al + b0 + 8 * A_STRIDE + 16);
                }
                uint32_t whi[4][2], wlo[4][2];
#pragma unroll
                for (int nf = 0; nf < 4; nf++) {
                    int n = wn * 32 + nf * 8 + g;
                    int o0 = w_off(n, kk >> 1);
                    int o1 = w_off(n, (kk + 8) >> 1);
                    whi[nf][0] = *(const uint32_t*)(Wh + o0);
                    whi[nf][1] = *(const uint32_t*)(Wh + o1);
                    wlo[nf][0] = *(const uint32_t*)(Wl + o0);
                    wlo[nf][1] = *(const uint32_t*)(Wl + o1);
                }
#pragma unroll
                for (int mi = 0; mi < 2; mi++)
#pragma unroll
                    for (int nf = 0; nf < 4; nf++) {
                        mma16816(acc[mi][nf], ahi[mi], whi[nf]);
                        mma16816(acc[mi][nf], alo[mi], whi[nf]);
                        mma16816(acc[mi][nf], ahi[mi], wlo[nf]);
                    }
            }
        }
        __syncthreads();
        // store next stage
        if (s + 1 < S) {
            char* bp = smem + ((s + 1) & 1) * BUF_SZ;
            int ab = arow * A_STRIDE + 2 * ak;
            *(uint32_t*)(bp + OFF_A_HI + ab)      = pack_hi2(aq0.x, aq0.y);
            *(uint32_t*)(bp + OFF_A_HI + ab + 4)  = pack_hi2(aq0.z, aq0.w);
            *(uint32_t*)(bp + OFF_A_HI + ab + 8)  = pack_hi2(aq1.x, aq1.y);
            *(uint32_t*)(bp + OFF_A_HI + ab + 12) = pack_hi2(aq1.z, aq1.w);
            *(uint32_t*)(bp + OFF_A_LO + ab)      = pack_lo2(aq0.x, aq0.y);
            *(uint32_t*)(bp + OFF_A_LO + ab + 4)  = pack_lo2(aq0.z, aq0.w);
            *(uint32_t*)(bp + OFF_A_LO + ab + 8)  = pack_lo2(aq1.x, aq1.y);
            *(uint32_t*)(bp + OFF_A_LO + ab + 12) = pack_lo2(aq1.z, aq1.w);
            const float* wv = (const float*)wq;
#pragma unroll
            for (int i = 0; i < 4; i++) {
                int k = wkb + 8 * i;
#pragma unroll
                for (int j = 0; j < 4; j++) {
                    float x = wv[i * 4 + j];
                    int n = wn4 + j;
                    int off = w_off(n, k >> 1) + (k & 1) * 2;
                    __nv_bfloat16 hx = __float2bfloat16(x);
                    __nv_bfloat16 lx = __float2bfloat16(x - __bfloat162float(hx));
                    *(uint16_t*)(bp + OFF_W_HI + off) = __bfloat16_as_ushort(hx);
                    *(uint16_t*)(bp + OFF_W_LO + off) = __bfloat16_as_ushort(lx);
                }
            }
            __syncthreads();
        }
    }

    // ---- epilogue ----
    float* Cb = (dsel == 0) ? g_hid : ((dsel == 1) ? g_toolres : Cext);
#pragma unroll
    for (int mi = 0; mi < 2; mi++) {
#pragma unroll
        for (int h = 0; h < 2; h++) {
            int m = m0 + wm * 32 + mi * 16 + g + 8 * h;
            bool ok = !(do_scatter && m >= Meff);
            if (!ok) continue;
            long orow = do_scatter ? (long)g_active[m] : (long)m;
            float* rp = Cb + orow * ldc;
#pragma unroll
            for (int nf = 0; nf < 4; nf++) {
                int n = n0 + wn * 32 + nf * 8 + j2 * 2;
                float2 v;
                v.x = acc[mi][nf][h * 2 + 0] + bias[n];
                v.y = acc[mi][nf][h * 2 + 1] + bias[n + 1];
                if (do_relu) { v.x = fmaxf(v.x, 0.f); v.y = fmaxf(v.y, 0.f); }
                *(float2*)(rp + n) = v;
            }
        }
    }
}

// ---------------- launch ----------------
extern "C" void kernel_launch(void* const* d_in, const int* in_sizes, int n_in,
                              void* d_out, int out_size)
{
    const float* hidden = (const float*)d_in[0];
    const float* emb    = (const float*)d_in[1];
    const float* gate_w = (const float*)d_in[2];
    const float* gate_b = (const float*)d_in[3];
    const float* sel_w1 = (const float*)d_in[4];
    const float* sel_b1 = (const float*)d_in[5];
    const float* sel_w2 = (const float*)d_in[6];
    const float* sel_b2 = (const float*)d_in[7];
    const float* pg_w1  = (const float*)d_in[8];
    const float* pg_b1  = (const float*)d_in[9];
    const float* pg_w2  = (const float*)d_in[10];
    const float* pg_b2  = (const float*)d_in[11];
    const float* ri_w1  = (const float*)d_in[12];
    const float* ri_b1  = (const float*)d_in[13];
    const float* ri_w2  = (const float*)d_in[14];
    const float* ri_b2  = (const float*)d_in[15];

    float* out        = (float*)d_out;
    float* out_enh    = out;
    float* out_probs  = ((long)out_size >= (long)NT * (H + T))     ? out + (long)NT * H       : nullptr;
    float* out_should = ((long)out_size >= (long)NT * (H + T + 1)) ? out + (long)NT * (H + T) : nullptr;

    cudaFuncSetAttribute(mma_gemm_kernel, cudaFuncAttributeMaxDynamicSharedMemorySize, MMA_SMEM);

    // 0) reset compaction counter
    init_kernel<<<1, 1>>>();

    // 1) enhanced = hidden (default) + gate dot product, fused
    copy_gate_kernel<<<NT, 256>>>(hidden, gate_w, out_enh);

    // 2) sel1 (fp32 exact): h1 = relu(hidden @ sel_w1 + b1) -> g_hid [NT,512]
    gemm_kernel<<<dim3(THID / 128, NT / 128), 256>>>(
        0, 0, 1, hidden, H, sel_w1, THID, sel_b1, THID, H);

    // 3) sel2 (fp32 exact): logits = g_hid @ sel_w2 + b2 -> g_logits [NT,128]
    gemm_kernel<<<dim3(T / 128, NT / 128), 256>>>(
        1, 3, 0, nullptr, THID, sel_w2, T, sel_b2, T, THID);

    // 4) top-3 + softmax + gate + compaction
    topk_kernel<<<NT / 8, 256>>>(gate_b, out_probs, out_should);

    // 5) pg1 (mma): relu(concat(h, emb[tool]) @ pg_w1 + b1) -> g_hid (compact)
    mma_gemm_kernel<<<dim3(THID / 128, NT / 64), 256, MMA_SMEM>>>(
        1, 0, 0, 1, 0, hidden, H, emb, H, pg_w1, THID, pg_b1, nullptr, THID, H + E);

    // 6) pg2 (mma): tool_result = g_hid @ pg_w2 + b2 -> g_toolres
    mma_gemm_kernel<<<dim3(H / 128, NT / 64), 256, MMA_SMEM>>>(
        0, 1, 1, 0, 0, nullptr, THID, nullptr, THID, pg_w2, H, pg_b2, nullptr, H, THID);

    // 7) ri1 (mma): relu(concat(h, tool_result) @ ri_w1 + b1) -> g_hid
    mma_gemm_kernel<<<dim3(THID / 128, NT / 64), 256, MMA_SMEM>>>(
        2, 0, 0, 1, 0, hidden, H, nullptr, H, ri_w1, THID, ri_b1, nullptr, THID, 2 * H);

    // 8) ri2 (mma): integrated = g_hid @ ri_w2 + b2, scatter into enhanced
    mma_gemm_kernel<<<dim3(H / 128, NT / 64), 256, MMA_SMEM>>>(
        0, 1, 2, 0, 1, nullptr, THID, nullptr, THID, ri_w2, H, ri_b2, out_enh, H, THID);
}

// round 4
// speedup vs baseline: 1.5717x; 1.0019x over previous
#include <cuda_runtime.h>
#include <cuda_bf16.h>
#include <math.h>
#include <stdint.h>

// ---------------- problem constants ----------------
#define NT   16384      // B*S tokens
#define H    2048
#define E    256
#define THID 512
#define T    128
#define NREG 64         // NUM_REGISTERED_TOOLS

// ---------------- scratch (device globals: no allocs allowed) ----------------
__device__ float g_hid[(long)NT * THID];      // 32 MB: sel-h1, then pg-h1 / ri-h1 (compact)
__device__ float g_toolres[(long)NT * H];     // 128 MB
__device__ float g_logits[(long)NT * T];      // 8 MB
__device__ float g_gate[NT];
__device__ int   g_active[NT];
__device__ int   g_tool[NT];
__device__ int   g_count[1];

// ---------------- tiny kernels ----------------
__global__ void init_kernel() { g_count[0] = 0; }

// copy hidden -> out AND compute gate dot product (single pass over hidden)
__global__ __launch_bounds__(256) void copy_gate_kernel(
    const float* __restrict__ src, const float* __restrict__ gw,
    float* __restrict__ dst)
{
    __shared__ float red[8];
    int t = blockIdx.x, tid = threadIdx.x;
    long base = (long)t * H + tid * 8;
    float4 a = *(const float4*)(src + base);
    float4 b = *(const float4*)(src + base + 4);
    *(float4*)(dst + base)     = a;
    *(float4*)(dst + base + 4) = b;
    float4 w0 = *(const float4*)(gw + tid * 8);
    float4 w1 = *(const float4*)(gw + tid * 8 + 4);
    float acc = a.x*w0.x + a.y*w0.y + a.z*w0.z + a.w*w0.w
              + b.x*w1.x + b.y*w1.y + b.z*w1.z + b.w*w1.w;
#pragma unroll
    for (int off = 16; off >= 1; off >>= 1)
        acc += __shfl_xor_sync(0xffffffffu, acc, off);
    if ((tid & 31) == 0) red[tid >> 5] = acc;
    __syncthreads();
    if (tid == 0) {
        float s = 0.f;
#pragma unroll
        for (int i = 0; i < 8; i++) s += red[i];
        g_gate[t] = s;
    }
}

// top-k/softmax/gate/compaction: one warp per token, reads g_logits
__global__ __launch_bounds__(256) void topk_kernel(
    const float* __restrict__ gate_b,
    float* __restrict__ out_probs, float* __restrict__ out_should)
{
    int t = blockIdx.x * 8 + (threadIdx.x >> 5);
    int l = threadIdx.x & 31;
    float4 v = *(const float4*)(g_logits + (long)t * T + l * 4);
    float lg[4] = {v.x, v.y, v.z, v.w};
    int topi[3];
    unsigned mask = 0;
    float mx = 0.f;
#pragma unroll
    for (int r = 0; r < 3; r++) {
        float bv = -3.4e38f; int bi = 1 << 30;
#pragma unroll
        for (int j = 0; j < 4; j++) {
            if (!((mask >> j) & 1)) {
                int c = l * 4 + j;
                if (lg[j] > bv || (lg[j] == bv && c < bi)) { bv = lg[j]; bi = c; }
            }
        }
#pragma unroll
        for (int off = 16; off >= 1; off >>= 1) {
            float ov = __shfl_xor_sync(0xffffffffu, bv, off);
            int   oi = __shfl_xor_sync(0xffffffffu, bi, off);
            if (ov > bv || (ov == bv && oi < bi)) { bv = ov; bi = oi; }
        }
        if (r == 0) mx = bv;
        topi[r] = bi;
        if ((bi >> 2) == l) mask |= 1u << (bi & 3);
    }
    float e[4], s = 0.f;
#pragma unroll
    for (int j = 0; j < 4; j++) { e[j] = expf(lg[j] - mx); s += e[j]; }
#pragma unroll
    for (int off = 16; off >= 1; off >>= 1)
        s += __shfl_xor_sync(0xffffffffu, s, off);
    if (out_probs)
        *(float4*)(out_probs + (long)t * T + l * 4) = make_float4(e[0]/s, e[1]/s, e[2]/s, e[3]/s);
    if (l == 0) {
        bool should = (g_gate[t] + gate_b[0]) > 0.f;
        if (out_should) out_should[t] = should ? 1.0f : 0.0f;
        int last = -1, tool = 0;
#pragma unroll
        for (int k = 0; k < 3; k++)
            if (should && topi[k] < NREG) { last = k; tool = topi[k]; }
        if (last >= 0) {
            int pos = atomicAdd(g_count, 1);
            g_active[pos] = t;
            g_tool[pos]   = tool;
        }
    }
}

// ---------------- fp32 FFMA GEMM (selector path: exactness protects top-k) ----------------
// asel: 0 A=Aext, 1 A=g_hid.   dsel: 0 g_hid, 3 g_logits
__global__ __launch_bounds__(256, 2) void gemm_kernel(
    int asel, int dsel, int do_relu,
    const float* __restrict__ Aext, int lda,
    const float* __restrict__ W, int ldw,    // [K, N] row-major
    const float* __restrict__ bias,
    int ldc, int K)
{
    __shared__ float As[16][132];
    __shared__ float Ws[16][128];

    int m0 = blockIdx.y * 128;
    int n0 = blockIdx.x * 128;
    int tid = threadIdx.x;
    const float* A0 = asel ? g_hid : Aext;

    int ra = tid >> 2;
    int kq = (tid & 3) * 4;
    const float* baseP[2];
#pragma unroll
    for (int i = 0; i < 2; i++)
        baseP[i] = A0 + (long)(m0 + ra + i * 64) * lda;

    int wk = tid >> 5;
    int wn = (tid & 31) * 4;

    float acc[8][8];
#pragma unroll
    for (int i = 0; i < 8; i++)
#pragma unroll
        for (int j = 0; j < 8; j++) acc[i][j] = 0.f;

    int tx = tid & 15, ty = tid >> 4;

    for (int k0 = 0; k0 < K; k0 += 16) {
#pragma unroll
        for (int i = 0; i < 2; i++) {
            float4 v = *(const float4*)(baseP[i] + k0 + kq);
            int m = ra + i * 64;
            As[kq + 0][m] = v.x; As[kq + 1][m] = v.y;
            As[kq + 2][m] = v.z; As[kq + 3][m] = v.w;
        }
#pragma unroll
        for (int i = 0; i < 2; i++) {
            int k = wk + i * 8;
            float4 v = *(const float4*)(W + (long)(k0 + k) * ldw + n0 + wn);
            *(float4*)&Ws[k][wn] = v;
        }
        __syncthreads();
#pragma unroll
        for (int kk = 0; kk < 16; kk++) {
            float a[8], b[8];
            *(float4*)(a)     = *(const float4*)&As[kk][ty * 8];
            *(float4*)(a + 4) = *(const float4*)&As[kk][ty * 8 + 4];
            *(float4*)(b)     = *(const float4*)&Ws[kk][tx * 8];
            *(float4*)(b + 4) = *(const float4*)&Ws[kk][tx * 8 + 4];
#pragma unroll
            for (int i = 0; i < 8; i++)
#pragma unroll
                for (int j = 0; j < 8; j++)
                    acc[i][j] = fmaf(a[i], b[j], acc[i][j]);
        }
        __syncthreads();
    }

    float* Cbase = (dsel == 0) ? g_hid : g_logits;
#pragma unroll
    for (int i = 0; i < 8; i++) {
        long row = m0 + ty * 8 + i;
        float* cp = Cbase + row * ldc + n0 + tx * 8;
#pragma unroll
        for (int jj = 0; jj < 8; jj += 4) {
            float4 v;
            v.x = acc[i][jj + 0] + bias[n0 + tx * 8 + jj + 0];
            v.y = acc[i][jj + 1] + bias[n0 + tx * 8 + jj + 1];
            v.z = acc[i][jj + 2] + bias[n0 + tx * 8 + jj + 2];
            v.w = acc[i][jj + 3] + bias[n0 + tx * 8 + jj + 3];
            if (do_relu) {
                v.x = fmaxf(v.x, 0.f); v.y = fmaxf(v.y, 0.f);
                v.z = fmaxf(v.z, 0.f); v.w = fmaxf(v.w, 0.f);
            }
            *(float4*)(cp + jj) = v;
        }
    }
}

// ---------------- mma.sync bf16 3-pass GEMM (pg/ri path, value-only precision) ----------------
// CTA tile M=64, N=128, Kstage=32, double-buffered smem.
// Split: x = hi + lo (bf16); D += Ahi*Whi + Alo*Whi + Ahi*Wlo  (error ~2^-18).
// mode: 0 direct rows, 1 gather token + concat emb, 2 gather token + concat toolres
// asel: 0 A=Aext, 1 A=g_hid.   dsel: 0 g_hid, 1 g_toolres, 2 Cext(+scatter)

#define A_STRIDE 72                     // bytes per A smem row (32 bf16 + pad)
#define W_STRIDE 68                     // bytes per W smem row (32 bf16 + pad)
#define OFF_A_HI 0
#define OFF_A_LO (64 * A_STRIDE)                    // 4608
#define OFF_W_HI (2 * 64 * A_STRIDE)                // 9216
#define OFF_W_LO (OFF_W_HI + 128 * W_STRIDE)        // 17920
#define BUF_SZ   (OFF_W_LO + 128 * W_STRIDE)        // 26624
#define MMA_SMEM (2 * BUF_SZ)                       // 53248

// W smem bank swizzle: kp (= k>>1) XORed with bits 5..6 of n (store-conflict-free)
__device__ __forceinline__ int w_off(int n, int kp) {
    return n * W_STRIDE + 4 * (kp ^ ((n >> 5) & 3));
}

__device__ __forceinline__ void mma16816(float* c, const uint32_t* a, const uint32_t* b) {
    asm volatile(
        "mma.sync.aligned.m16n8k16.row.col.f32.bf16.bf16.f32 "
        "{%0,%1,%2,%3}, {%4,%5,%6,%7}, {%8,%9}, {%0,%1,%2,%3};\n"
        : "+f"(c[0]), "+f"(c[1]), "+f"(c[2]), "+f"(c[3])
        : "r"(a[0]), "r"(a[1]), "r"(a[2]), "r"(a[3]), "r"(b[0]), "r"(b[1]));
}

__device__ __forceinline__ uint32_t pack_hi2(float x, float y) {
    __nv_bfloat16 hx = __float2bfloat16(x), hy = __float2bfloat16(y);
    return (uint32_t)__bfloat16_as_ushort(hx) | ((uint32_t)__bfloat16_as_ushort(hy) << 16);
}
__device__ __forceinline__ uint32_t pack_lo2(float x, float y) {
    __nv_bfloat16 hx = __float2bfloat16(x), hy = __float2bfloat16(y);
    __nv_bfloat16 lx = __float2bfloat16(x - __bfloat162float(hx));
    __nv_bfloat16 ly = __float2bfloat16(y - __bfloat162float(hy));
    return (uint32_t)__bfloat16_as_ushort(lx) | ((uint32_t)__bfloat16_as_ushort(ly) << 16);
}

__global__ __launch_bounds__(256) void mma_gemm_kernel(
    int mode, int asel, int dsel, int do_relu, int do_scatter,
    const float* __restrict__ Aext, int lda,
    const float* __restrict__ Bsec, int splitK,
    const float* __restrict__ W, int ldw,
    const float* __restrict__ bias,
    float* __restrict__ Cext, int ldc, int K)
{
    extern __shared__ __align__(16) char smem[];
    int Meff = g_count[0];
    int m0 = blockIdx.y * 64;
    if (m0 >= Meff) return;
    int n0 = blockIdx.x * 128;
    int tid = threadIdx.x;
    int wid = tid >> 5;
    int lane = tid & 31;
    int wm = wid & 1;       // m half (32 rows)
    int wn = wid >> 1;      // n quarter (32 cols)

    // ---- A loader mapping: 4 threads per row, 8 k's each ----
    int arow = tid >> 2;
    int ak   = (tid & 3) * 8;
    const float* A0 = asel ? g_hid : Aext;
    const float* prim;
    const float* sec;
    {
        int rg = m0 + arow;
        if (mode == 0) {
            prim = A0 + (long)rg * lda;
            sec  = prim;
        } else {
            int rr  = (rg < Meff) ? rg : (Meff - 1);
            int tok = g_active[rr];
            prim = Aext + (long)tok * lda;
            sec  = (mode == 1) ? (Bsec + (long)g_tool[rr] * E)
                               : (g_toolres + (long)rr * H);
        }
    }
    // ---- W loader mapping: 32 threads across n (coalesced), 8 k rows base ----
    int wn4 = (tid & 31) * 4;
    int wkb = tid >> 5;

    float4 aq0, aq1;
    float4 wq[4];
    int S = K / 32;

    float acc[2][4][4];
#pragma unroll
    for (int i = 0; i < 2; i++)
#pragma unroll
        for (int j = 0; j < 4; j++)
#pragma unroll
            for (int q = 0; q < 4; q++) acc[i][j][q] = 0.f;

    // ---- prologue: load + store stage 0 ----
    {
        int k0 = ak;
        const float* src = (k0 < splitK) ? (prim + k0) : (sec + (k0 - splitK));
        aq0 = *(const float4*)(src);
        aq1 = *(const float4*)(src + 4);
#pragma unroll
        for (int i = 0; i < 4; i++)
            wq[i] = *(const float4*)(W + (long)(wkb + 8 * i) * ldw + n0 + wn4);
    }
    {
        char* bp = smem;
        int ab = arow * A_STRIDE + 2 * ak;
        *(uint32_t*)(bp + OFF_A_HI + ab)      = pack_hi2(aq0.x, aq0.y);
        *(uint32_t*)(bp + OFF_A_HI + ab + 4)  = pack_hi2(aq0.z, aq0.w);
        *(uint32_t*)(bp + OFF_A_HI + ab + 8)  = pack_hi2(aq1.x, aq1.y);
        *(uint32_t*)(bp + OFF_A_HI + ab + 12) = pack_hi2(aq1.z, aq1.w);
        *(uint32_t*)(bp + OFF_A_LO + ab)      = pack_lo2(aq0.x, aq0.y);
        *(uint32_t*)(bp + OFF_A_LO + ab + 4)  = pack_lo2(aq0.z, aq0.w);
        *(uint32_t*)(bp + OFF_A_LO + ab + 8)  = pack_lo2(aq1.x, aq1.y);
        *(uint32_t*)(bp + OFF_A_LO + ab + 12) = pack_lo2(aq1.z, aq1.w);
        const float* wv = (const float*)wq;
#pragma unroll
        for (int i = 0; i < 4; i++) {
            int k = wkb + 8 * i;
#pragma unroll
            for (int j = 0; j < 4; j++) {
                float x = wv[i * 4 + j];
                int n = wn4 + j;
                int off = w_off(n, k >> 1) + (k & 1) * 2;
                __nv_bfloat16 hx = __float2bfloat16(x);
                __nv_bfloat16 lx = __float2bfloat16(x - __bfloat162float(hx));
                *(uint16_t*)(bp + OFF_W_HI + off) = __bfloat16_as_ushort(hx);
                *(uint16_t*)(bp + OFF_W_LO + off) = __bfloat16_as_ushort(lx);
            }
        }
    }
    __syncthreads();

    int g  = lane >> 2;
    int j2 = lane & 3;

    for (int s = 0; s < S; s++) {
        // prefetch next stage into registers
        if (s + 1 < S) {
            int k0 = (s + 1) * 32 + ak;
            const float* src = (k0 < splitK) ? (prim + k0) : (sec + (k0 - splitK));
            aq0 = *(const float4*)(src);
            aq1 = *(const float4*)(src + 4);
#pragma unroll
            for (int i = 0; i < 4; i++)
                wq[i] = *(const float4*)(W + (long)((s + 1) * 32 + wkb + 8 * i) * ldw + n0 + wn4);
        }
        // compute current stage
        {
            char* bp = smem + (s & 1) * BUF_SZ;
            const char* Ah = bp + OFF_A_HI;
            const char* Al = bp + OFF_A_LO;
            const char* Wh = bp + OFF_W_HI;
            const char* Wl = bp + OFF_W_LO;
#pragma unroll
            for (int ks = 0; ks < 2; ks++) {
                int kk = ks * 16 + j2 * 2;
                uint32_t ahi[2][4], alo[2][4];
#pragma unroll
                for (int mi = 0; mi < 2; mi++) {
                    int row = wm * 32 + mi * 16 + g;
                    int b0 = row * A_STRIDE + 2 * kk;
                    ahi[mi][0] = *(const uint32_t*)(Ah + b0);
                    ahi[mi][1] = *(const uint32_t*)(Ah + b0 + 8 * A_STRIDE);
                    ahi[mi][2] = *(const uint32_t*)(Ah + b0 + 16);
                    ahi[mi][3] = *(const uint32_t*)(Ah + b0 + 8 * A_STRIDE + 16);
                    alo[mi][0] = *(const uint32_t*)(Al + b0);
                    alo[mi][1] = *(const uint32_t*)(Al + b0 + 8 * A_STRIDE);
                    alo[mi][2] = *(const uint32_t*)(Al + b0 + 16);
                    alo[mi][3] = *(const uint32_t*)(Al + b0 + 8 * A_STRIDE + 16);
                }
                uint32_t whi[4][2], wlo[4][2];
#pragma unroll
                for (int nf = 0; nf < 4; nf++) {
                    int n = wn * 32 + nf * 8 + g;
                    int o0 = w_off(n, kk >> 1);
                    int o1 = w_off(n, (kk + 8) >> 1);
                    whi[nf][0] = *(const uint32_t*)(Wh + o0);
                    whi[nf][1] = *(const uint32_t*)(Wh + o1);
                    wlo[nf][0] = *(const uint32_t*)(Wl + o0);
                    wlo[nf][1] = *(const uint32_t*)(Wl + o1);
                }
#pragma unroll
                for (int mi = 0; mi < 2; mi++)
#pragma unroll
                    for (int nf = 0; nf < 4; nf++) {
                        mma16816(acc[mi][nf], ahi[mi], whi[nf]);
                        mma16816(acc[mi][nf], alo[mi], whi[nf]);
                        mma16816(acc[mi][nf], ahi[mi], wlo[nf]);
                    }
            }
        }
        __syncthreads();
        // store next stage
        if (s + 1 < S) {
            char* bp = smem + ((s + 1) & 1) * BUF_SZ;
            int ab = arow * A_STRIDE + 2 * ak;
            *(uint32_t*)(bp + OFF_A_HI + ab)      = pack_hi2(aq0.x, aq0.y);
            *(uint32_t*)(bp + OFF_A_HI + ab + 4)  = pack_hi2(aq0.z, aq0.w);
            *(uint32_t*)(bp + OFF_A_HI + ab + 8)  = pack_hi2(aq1.x, aq1.y);
            *(uint32_t*)(bp + OFF_A_HI + ab + 12) = pack_hi2(aq1.z, aq1.w);
            *(uint32_t*)(bp + OFF_A_LO + ab)      = pack_lo2(aq0.x, aq0.y);
            *(uint32_t*)(bp + OFF_A_LO + ab + 4)  = pack_lo2(aq0.z, aq0.w);
            *(uint32_t*)(bp + OFF_A_LO + ab + 8)  = pack_lo2(aq1.x, aq1.y);
            *(uint32_t*)(bp + OFF_A_LO + ab + 12) = pack_lo2(aq1.z, aq1.w);
            const float* wv = (const float*)wq;
#pragma unroll
            for (int i = 0; i < 4; i++) {
                int k = wkb + 8 * i;
#pragma unroll
                for (int j = 0; j < 4; j++) {
                    float x = wv[i * 4 + j];
                    int n = wn4 + j;
                    int off = w_off(n, k >> 1) + (k & 1) * 2;
                    __nv_bfloat16 hx = __float2bfloat16(x);
                    __nv_bfloat16 lx = __float2bfloat16(x - __bfloat162float(hx));
                    *(uint16_t*)(bp + OFF_W_HI + off) = __bfloat16_as_ushort(hx);
                    *(uint16_t*)(bp + OFF_W_LO + off) = __bfloat16_as_ushort(lx);
                }
            }
            __syncthreads();
        }
    }

    // ---- epilogue ----
    float* Cb = (dsel == 0) ? g_hid : ((dsel == 1) ? g_toolres : Cext);
#pragma unroll
    for (int mi = 0; mi < 2; mi++) {
#pragma unroll
        for (int h = 0; h < 2; h++) {
            int m = m0 + wm * 32 + mi * 16 + g + 8 * h;
            bool ok = !(do_scatter && m >= Meff);
            if (!ok) continue;
            long orow = do_scatter ? (long)g_active[m] : (long)m;
            float* rp = Cb + orow * ldc;
#pragma unroll
            for (int nf = 0; nf < 4; nf++) {
                int n = n0 + wn * 32 + nf * 8 + j2 * 2;
                float2 v;
                v.x = acc[mi][nf][h * 2 + 0] + bias[n];
                v.y = acc[mi][nf][h * 2 + 1] + bias[n + 1];
                if (do_relu) { v.x = fmaxf(v.x, 0.f); v.y = fmaxf(v.y, 0.f); }
                *(float2*)(rp + n) = v;
            }
        }
    }
}

// ---------------- launch ----------------
extern "C" void kernel_launch(void* const* d_in, const int* in_sizes, int n_in,
                              void* d_out, int out_size)
{
    const float* hidden = (const float*)d_in[0];
    const float* emb    = (const float*)d_in[1];
    const float* gate_w = (const float*)d_in[2];
    const float* gate_b = (const float*)d_in[3];
    const float* sel_w1 = (const float*)d_in[4];
    const float* sel_b1 = (const float*)d_in[5];
    const float* sel_w2 = (const float*)d_in[6];
    const float* sel_b2 = (const float*)d_in[7];
    const float* pg_w1  = (const float*)d_in[8];
    const float* pg_b1  = (const float*)d_in[9];
    const float* pg_w2  = (const float*)d_in[10];
    const float* pg_b2  = (const float*)d_in[11];
    const float* ri_w1  = (const float*)d_in[12];
    const float* ri_b1  = (const float*)d_in[13];
    const float* ri_w2  = (const float*)d_in[14];
    const float* ri_b2  = (const float*)d_in[15];

    float* out        = (float*)d_out;
    float* out_enh    = out;
    float* out_probs  = ((long)out_size >= (long)NT * (H + T))     ? out + (long)NT * H       : nullptr;
    float* out_should = ((long)out_size >= (long)NT * (H + T + 1)) ? out + (long)NT * (H + T) : nullptr;

    cudaFuncSetAttribute(mma_gemm_kernel, cudaFuncAttributeMaxDynamicSharedMemorySize, MMA_SMEM);

    // 0) reset compaction counter
    init_kernel<<<1, 1>>>();

    // 1) enhanced = hidden (default) + gate dot product, fused
    copy_gate_kernel<<<NT, 256>>>(hidden, gate_w, out_enh);

    // 2) sel1 (fp32 exact): h1 = relu(hidden @ sel_w1 + b1) -> g_hid [NT,512]
    gemm_kernel<<<dim3(THID / 128, NT / 128), 256>>>(
        0, 0, 1, hidden, H, sel_w1, THID, sel_b1, THID, H);

    // 3) sel2 (fp32 exact): logits = g_hid @ sel_w2 + b2 -> g_logits [NT,128]
    gemm_kernel<<<dim3(T / 128, NT / 128), 256>>>(
        1, 3, 0, nullptr, THID, sel_w2, T, sel_b2, T, THID);

    // 4) top-3 + softmax + gate + compaction
    topk_kernel<<<NT / 8, 256>>>(gate_b, out_probs, out_should);

    // 5) pg1 (mma): relu(concat(h, emb[tool]) @ pg_w1 + b1) -> g_hid (compact)
    mma_gemm_kernel<<<dim3(THID / 128, NT / 64), 256, MMA_SMEM>>>(
        1, 0, 0, 1, 0, hidden, H, emb, H, pg_w1, THID, pg_b1, nullptr, THID, H + E);

    // 6) pg2 (mma): tool_result = g_hid @ pg_w2 + b2 -> g_toolres
    mma_gemm_kernel<<<dim3(H / 128, NT / 64), 256, MMA_SMEM>>>(
        0, 1, 1, 0, 0, nullptr, THID, nullptr, THID, pg_w2, H, pg_b2, nullptr, H, THID);

    // 7) ri1 (mma): relu(concat(h, tool_result) @ ri_w1 + b1) -> g_hid
    mma_gemm_kernel<<<dim3(THID / 128, NT / 64), 256, MMA_SMEM>>>(
        2, 0, 0, 1, 0, hidden, H, nullptr, H, ri_w1, THID, ri_b1, nullptr, THID, 2 * H);

    // 8) ri2 (mma): integrated = g_hid @ ri_w2 + b2, scatter into enhanced
    mma_gemm_kernel<<<dim3(H / 128, NT / 64), 256, MMA_SMEM>>>(
        0, 1, 2, 0, 1, nullptr, THID, nullptr, THID, ri_w2, H, ri_b2, out_enh, H, THID);
}